// round 5
// baseline (speedup 1.0000x reference)
#include <cuda_runtime.h>
#include <cuda_bf16.h>

#define N_NODES 100000
#define N_EDGES 1600000
#define COUT 64
#define CIN 128
#define NBLK_SCAN 391   // ceil(100000/256)

// ---------------- scratch (no allocations allowed) ----------------
__device__ int   g_degi[N_NODES];                // edge in-degree (no self loop)
__device__ float g_dinv[N_NODES];
__device__ float g_xs[(size_t)N_NODES * COUT];   // xw * dinv[row], gather source
__device__ int   g_off[N_NODES];                 // CSR offsets (by target)
__device__ int   g_cnt[N_NODES];                 // fill counters -> in-degree
__device__ int   g_srow[N_EDGES];                // CSR-sorted source row ids
__device__ int   g_bsum[512];
__device__ int   g_bscan[512];
__device__ float g_sums[COUT];
__device__ float g_sumsq[COUT];
__device__ float g_A[COUT];
__device__ float g_B[COUT];

// packed f32x2 helpers
__device__ __forceinline__ unsigned long long pack_dup(float x) {
    unsigned long long p;
    unsigned u = __float_as_uint(x);
    asm("mov.b64 %0, {%1, %1};" : "=l"(p) : "r"(u));
    return p;
}
__device__ __forceinline__ void ffma2(unsigned long long& d,
                                      unsigned long long a,
                                      unsigned long long b) {
    asm("fma.rn.f32x2 %0, %1, %2, %3;" : "=l"(d) : "l"(a), "l"(b), "l"(d));
}
__device__ __forceinline__ void unpack2(unsigned long long p, float& lo, float& hi) {
    unsigned a, b2;
    asm("mov.b64 {%0, %1}, %2;" : "=r"(a), "=r"(b2) : "l"(p));
    lo = __uint_as_float(a);
    hi = __uint_as_float(b2);
}

// ---------------- 1. init ----------------
__global__ void k_init() {
    int i = blockIdx.x * blockDim.x + threadIdx.x;
    if (i < N_NODES) { g_degi[i] = 0; g_cnt[i] = 0; }
    if (i < COUT) { g_sums[i] = 0.0f; g_sumsq[i] = 0.0f; }
}

// ---------------- 2. degree count over targets (int) ----------------
__global__ void k_deg(const int* __restrict__ col) {
    int e = blockIdx.x * blockDim.x + threadIdx.x;
    if (e < N_EDGES) atomicAdd(&g_degi[col[e]], 1);
}

// ---------------- 3a. per-block exclusive scan of in-degree + dinv ------------
__global__ void k_blockscan() {
    __shared__ int s[256];
    int tid = threadIdx.x;
    int i = blockIdx.x * 256 + tid;
    int v = 0;
    if (i < N_NODES) {
        v = g_degi[i];
        g_dinv[i] = rsqrtf((float)v + 1.0f);   // deg incl self loop
    }
    s[tid] = v;
    __syncthreads();
    #pragma unroll
    for (int d = 1; d < 256; d <<= 1) {
        int t = (tid >= d) ? s[tid - d] : 0;
        __syncthreads();
        s[tid] += t;
        __syncthreads();
    }
    if (i < N_NODES) g_off[i] = s[tid] - v;
    if (tid == 255) g_bsum[blockIdx.x] = s[255];
}

// ---------------- 3b. scan block sums (single block, 512 wide) ----------------
__global__ void k_scanb() {
    __shared__ int s[512];
    int tid = threadIdx.x;
    int v = (tid < NBLK_SCAN) ? g_bsum[tid] : 0;
    s[tid] = v;
    __syncthreads();
    #pragma unroll
    for (int d = 1; d < 512; d <<= 1) {
        int t = (tid >= d) ? s[tid - d] : 0;
        __syncthreads();
        s[tid] += t;
        __syncthreads();
    }
    g_bscan[tid] = s[tid] - v;   // exclusive
}

// ---------------- 3c. add block offsets ----------------
__global__ void k_offadd() {
    int i = blockIdx.x * 256 + threadIdx.x;
    if (i < N_NODES) g_off[i] += g_bscan[i >> 8];
}

// ---------------- 4. bin edges into CSR (by target) ----------------
__global__ void k_bin(const int* __restrict__ rowIdx, const int* __restrict__ colIdx) {
    int e = blockIdx.x * blockDim.x + threadIdx.x;
    if (e < N_EDGES) {
        int c = colIdx[e];
        int p = atomicAdd(&g_cnt[c], 1);
        g_srow[g_off[c] + p] = rowIdx[e];
    }
}

// ---------------- 5. GEMM: xs = (x @ W) * dinv[row] --------------------------
#define XPAD 260
__global__ void __launch_bounds__(256, 2) k_gemm(const float* __restrict__ x,
                                                 const float* __restrict__ W) {
    extern __shared__ float smem[];
    float* sW = smem;              // 8192 floats
    float* sX = smem + 8192;       // 32 * 260 floats
    const int tid = threadIdx.x;
    const int base = blockIdx.x * 256;

    {
        const float4* W4 = (const float4*)W;
        float4* sW4 = (float4*)sW;
        #pragma unroll
        for (int i = tid; i < 2048; i += 256) sW4[i] = W4[i];
    }

    const int c0 = (tid & 7) * 8;
    const int r0 = (tid >> 3) * 8;

    unsigned long long acc[8][4];
    #pragma unroll
    for (int j = 0; j < 8; j++)
        #pragma unroll
        for (int p = 0; p < 4; p++) acc[j][p] = 0ULL;

    const float4* x4 = (const float4*)x;

    for (int cc = 0; cc < 4; cc++) {
        const int k0 = cc * 32;
        __syncthreads();
        #pragma unroll
        for (int t = 0; t < 8; t++) {
            int idx = tid + t * 256;
            int r = idx >> 3;
            int kq = idx & 7;
            int row = base + r;
            float4 v = make_float4(0.f, 0.f, 0.f, 0.f);
            if (row < N_NODES) v = x4[row * 32 + (k0 >> 2) + kq];
            int kl = kq << 2;
            sX[(kl + 0) * XPAD + r] = v.x;
            sX[(kl + 1) * XPAD + r] = v.y;
            sX[(kl + 2) * XPAD + r] = v.z;
            sX[(kl + 3) * XPAD + r] = v.w;
        }
        __syncthreads();

        #pragma unroll 4
        for (int kk = 0; kk < 32; kk++) {
            const int k = k0 + kk;
            ulonglong2 wp0 = *(const ulonglong2*)&sW[k * 64 + c0];
            ulonglong2 wp1 = *(const ulonglong2*)&sW[k * 64 + c0 + 4];
            unsigned long long wv[4] = {wp0.x, wp0.y, wp1.x, wp1.y};
            float4 xv0 = *(const float4*)&sX[kk * XPAD + r0];
            float4 xv1 = *(const float4*)&sX[kk * XPAD + r0 + 4];
            float xr[8] = {xv0.x, xv0.y, xv0.z, xv0.w, xv1.x, xv1.y, xv1.z, xv1.w};
            #pragma unroll
            for (int j = 0; j < 8; j++) {
                unsigned long long xd = pack_dup(xr[j]);
                #pragma unroll
                for (int p = 0; p < 4; p++) ffma2(acc[j][p], xd, wv[p]);
            }
        }
    }

    #pragma unroll
    for (int j = 0; j < 8; j++) {
        int row = base + r0 + j;
        if (row < N_NODES) {
            float di = g_dinv[row];
            float o[8];
            #pragma unroll
            for (int p = 0; p < 4; p++) unpack2(acc[j][p], o[2 * p], o[2 * p + 1]);
            float4 v0 = make_float4(o[0] * di, o[1] * di, o[2] * di, o[3] * di);
            float4 v1 = make_float4(o[4] * di, o[5] * di, o[6] * di, o[7] * di);
            ((float4*)g_xs)[row * 16 + (c0 >> 2)] = v0;
            ((float4*)g_xs)[row * 16 + (c0 >> 2) + 1] = v1;
        }
    }
}

// ---------------- 6. CSR gather-aggregate + fused BN stats -------------------
// 16 lanes per node (one float4 channel group each). Edge indices are loaded
// once per 16-lane group (coalesced) and broadcast via shfl.
// CRITICAL: shfl mask covers ONLY this 16-lane half (the two halves of a warp
// process different nodes and diverge — a full-warp mask deadlocks).
__global__ void __launch_bounds__(256) k_agg(float* __restrict__ out,
                                             const float* __restrict__ b) {
    __shared__ float s1[COUT], s2[COUT];
    const int tid = threadIdx.x;
    if (tid < COUT) { s1[tid] = 0.f; s2[tid] = 0.f; }
    __syncthreads();

    const int comp = tid & 15;                    // lane within 16-group
    const unsigned gmask = 0xFFFFu << (tid & 16); // this half-warp only
    const float4 bb = ((const float4*)b)[comp];
    const float4* xs4 = (const float4*)g_xs;

    float sum0 = 0.f, sum1 = 0.f, sum2 = 0.f, sum3 = 0.f;
    float sq0 = 0.f, sq1 = 0.f, sq2 = 0.f, sq3 = 0.f;

    const int groups_per_blk = 256 / 16;
    const int gstride = gridDim.x * groups_per_blk;

    for (int node = blockIdx.x * groups_per_blk + (tid >> 4); node < N_NODES;
         node += gstride) {
        float4 acc = xs4[node * 16 + comp];   // self loop
        const int beg = g_off[node];
        const int cnt = g_cnt[node];
        int done = 0;
        while (done + 16 <= cnt) {
            int idx = g_srow[beg + done + comp];
            #pragma unroll
            for (int t = 0; t < 16; t++) {
                int r = __shfl_sync(gmask, idx, t, 16);
                float4 a = xs4[r * 16 + comp];
                acc.x += a.x; acc.y += a.y; acc.z += a.z; acc.w += a.w;
            }
            done += 16;
        }
        int rem = cnt - done;
        if (rem > 0) {
            int idx = (comp < rem) ? g_srow[beg + done + comp] : 0;
            for (int t = 0; t < rem; t++) {
                int r = __shfl_sync(gmask, idx, t, 16);
                float4 a = xs4[r * 16 + comp];
                acc.x += a.x; acc.y += a.y; acc.z += a.z; acc.w += a.w;
            }
        }
        const float di = g_dinv[node];
        acc.x *= di; acc.y *= di; acc.z *= di; acc.w *= di;
        ((float4*)out)[node * 16 + comp] = acc;

        float o0 = acc.x + bb.x, o1 = acc.y + bb.y;
        float o2 = acc.z + bb.z, o3 = acc.w + bb.w;
        sum0 += o0; sq0 += o0 * o0;
        sum1 += o1; sq1 += o1 * o1;
        sum2 += o2; sq2 += o2 * o2;
        sum3 += o3; sq3 += o3 * o3;
    }

    int cb = comp * 4;
    atomicAdd(&s1[cb + 0], sum0); atomicAdd(&s2[cb + 0], sq0);
    atomicAdd(&s1[cb + 1], sum1); atomicAdd(&s2[cb + 1], sq1);
    atomicAdd(&s1[cb + 2], sum2); atomicAdd(&s2[cb + 2], sq2);
    atomicAdd(&s1[cb + 3], sum3); atomicAdd(&s2[cb + 3], sq3);
    __syncthreads();
    if (tid < COUT) {
        atomicAdd(&g_sums[tid], s1[tid]);
        atomicAdd(&g_sumsq[tid], s2[tid]);
    }
}

// ---------------- 7. fold BN into per-channel affine ----------------
__global__ void k_fold(const float* __restrict__ b,
                       const float* __restrict__ gamma,
                       const float* __restrict__ beta) {
    int c = threadIdx.x;
    if (c < COUT) {
        float inv_n = 1.0f / (float)N_NODES;
        float mean = g_sums[c] * inv_n;
        float var = g_sumsq[c] * inv_n - mean * mean;
        float scale = gamma[c] * rsqrtf(var + 1e-5f);
        g_A[c] = scale;
        g_B[c] = scale * (b[c] - mean) + beta[c];
    }
}

// ---------------- 8. final: y = leaky(A*v + B), in place ----------------
__global__ void __launch_bounds__(256) k_final(float* __restrict__ out) {
    int q = blockIdx.x * 256 + threadIdx.x;
    if (q >= N_NODES * 16) return;
    int cq = q & 15;
    float4 a = ((const float4*)g_A)[cq];
    float4 bb = ((const float4*)g_B)[cq];
    float4 v = ((float4*)out)[q];
    float4 y;
    y.x = a.x * v.x + bb.x;
    y.y = a.y * v.y + bb.y;
    y.z = a.z * v.z + bb.z;
    y.w = a.w * v.w + bb.w;
    y.x = (y.x >= 0.f) ? y.x : 0.01f * y.x;
    y.y = (y.y >= 0.f) ? y.y : 0.01f * y.y;
    y.z = (y.z >= 0.f) ? y.z : 0.01f * y.z;
    y.w = (y.w >= 0.f) ? y.w : 0.01f * y.w;
    ((float4*)out)[q] = y;
}

extern "C" void kernel_launch(void* const* d_in, const int* in_sizes, int n_in,
                              void* d_out, int out_size) {
    const float* x      = (const float*)d_in[0];
    const int*   eidx   = (const int*)d_in[1];     // [2, E]: row then col
    const float* W      = (const float*)d_in[2];
    const float* b      = (const float*)d_in[3];
    const float* gamma  = (const float*)d_in[4];
    const float* beta   = (const float*)d_in[5];
    float* out = (float*)d_out;

    const int* rowIdx = eidx;
    const int* colIdx = eidx + N_EDGES;

    static bool attr_set = false;
    const int gemm_smem = (8192 + 32 * XPAD) * sizeof(float);   // 66048 B
    if (!attr_set) {
        cudaFuncSetAttribute(k_gemm, cudaFuncAttributeMaxDynamicSharedMemorySize, gemm_smem);
        attr_set = true;
    }

    k_init<<<(N_NODES + 255) / 256, 256>>>();
    k_deg<<<(N_EDGES + 255) / 256, 256>>>(colIdx);
    k_blockscan<<<NBLK_SCAN, 256>>>();
    k_scanb<<<1, 512>>>();
    k_offadd<<<NBLK_SCAN, 256>>>();
    k_bin<<<(N_EDGES + 255) / 256, 256>>>(rowIdx, colIdx);
    k_gemm<<<(N_NODES + 255) / 256, 256, gemm_smem>>>(x, W);
    k_agg<<<2048, 256>>>(out, b);
    k_fold<<<1, 64>>>(b, gamma, beta);
    k_final<<<(N_NODES * 16 + 255) / 256, 256>>>(out);
}